// round 3
// baseline (speedup 1.0000x reference)
#include <cuda_runtime.h>
#include <cstdint>

#define N_NODES 50000
#define N_EDGES 600000
#define N_TOT   (N_NODES + N_EDGES)
#define N_GRAPHS 256
#define D 128
#define NLAYER 4
#define BN_EPS 1e-5f
#define GEMM_BLOCKS ((N_NODES + 127) / 128)   /* 391 */

// ---------------- scratch (device globals; no dynamic alloc allowed) ----------------
__device__ float g_h[(size_t)N_NODES * D];     // h0 (atom emb), then z per layer (pre-BN)
__device__ float g_aggr[(size_t)N_NODES * D];  // tf32-rounded aggregation (GEMM A)
__device__ float g_Wt[D * D];                  // W transposed to [k][n], tf32-rounded
__device__ float g_ct[243 * D];                // combo bond-embedding table
__device__ float g_part[(size_t)GEMM_BLOCKS * 256]; // per-block col sums (128) + sumsq (128)
__device__ float g_scale[D];
__device__ float g_shift[D];
__device__ float g_pool[N_GRAPHS * D];
__device__ int   g_off[N_NODES + 1];
__device__ int   g_cur[N_NODES];
__device__ int   g_adj[N_TOT];                 // packed: src | (combo<<16)
__device__ int   g_bsums[64];
__device__ int   g_bounds[N_GRAPHS + 1];

__device__ __forceinline__ float tf32r(float x) {
    float y;
    asm("cvt.rna.tf32.f32 %0, %1;" : "=f"(y) : "f"(x));
    return y;
}

__device__ __forceinline__ void mma_tf32(float* c, const uint32_t* a, const uint32_t* b) {
    asm volatile(
        "mma.sync.aligned.m16n8k8.row.col.f32.tf32.tf32.f32 "
        "{%0,%1,%2,%3}, {%4,%5,%6,%7}, {%8,%9}, {%0,%1,%2,%3};"
        : "+f"(c[0]), "+f"(c[1]), "+f"(c[2]), "+f"(c[3])
        : "r"(a[0]), "r"(a[1]), "r"(a[2]), "r"(a[3]), "r"(b[0]), "r"(b[1]));
}

// ---------------- atom embedding (warp per node, float4 lanes) ----------------
__global__ void k_atom(const int* __restrict__ x, const float* __restrict__ aemb) {
    int gid = blockIdx.x * blockDim.x + threadIdx.x;
    int node = gid >> 5, lane = gid & 31;
    if (node >= N_NODES) return;
    const int* xi = x + (size_t)node * 9;
    float4 acc = make_float4(0.f, 0.f, 0.f, 0.f);
#pragma unroll
    for (int f = 0; f < 9; f++) {
        int v = __ldg(&xi[f]);
        float4 e = __ldg(&((const float4*)aemb)[(size_t)(f * 120 + v) * 32 + lane]);
        acc.x += e.x; acc.y += e.y; acc.z += e.z; acc.w += e.w;
    }
    ((float4*)g_h)[(size_t)node * 32 + lane] = acc;
}

// ---------------- CSR build ----------------
__global__ void k_initdeg() {
    int i = blockIdx.x * blockDim.x + threadIdx.x;
    if (i < N_NODES) g_off[i] = 1;   // self-loop
}
__global__ void k_hist(const int* __restrict__ e_dst) {
    int e = blockIdx.x * blockDim.x + threadIdx.x;
    if (e < N_EDGES) atomicAdd(&g_off[e_dst[e]], 1);
}
__global__ void k_scan1() {
    __shared__ int sh[1024];
    int t = threadIdx.x;
    int idx = blockIdx.x * 1024 + t;
    int v = (idx < N_NODES) ? g_off[idx] : 0;
    sh[t] = v;
    __syncthreads();
    for (int off = 1; off < 1024; off <<= 1) {
        int xv = (t >= off) ? sh[t - off] : 0;
        __syncthreads();
        sh[t] += xv;
        __syncthreads();
    }
    if (idx < N_NODES) g_off[idx] = sh[t] - v;
    if (t == 1023) g_bsums[blockIdx.x] = sh[1023];
}
__global__ void k_scan2(int nblk) {
    if (threadIdx.x == 0) {
        int run = 0;
        for (int i = 0; i < nblk; i++) { int tmp = g_bsums[i]; g_bsums[i] = run; run += tmp; }
    }
}
__global__ void k_scan3() {
    int i = blockIdx.x * blockDim.x + threadIdx.x;
    if (i < N_NODES) {
        int o = g_off[i] + g_bsums[i >> 10];
        g_off[i] = o;
        g_cur[i] = o;
    }
    if (i == 0) g_off[N_NODES] = N_TOT;
}
__global__ void k_scatter(const int* __restrict__ e_src, const int* __restrict__ e_dst,
                          const int* __restrict__ ea) {
    int t = blockIdx.x * blockDim.x + threadIdx.x;
    if (t >= N_TOT) return;
    int d, s, comb;
    if (t < N_EDGES) {
        s = e_src[t];
        d = e_dst[t];
        const int* a = ea + (size_t)t * 5;
        comb = a[0] + 3 * a[1] + 9 * a[2] + 27 * a[3] + 81 * a[4];
    } else {
        d = s = t - N_EDGES;
        comb = 0;
    }
    int pos = atomicAdd(&g_cur[d], 1);
    g_adj[pos] = s | (comb << 16);
}

// ---------------- per-layer prep: combo bond table + W^T tf32 ----------------
__global__ void k_prep(const float* __restrict__ bemb, const float* __restrict__ W) {
    int b = blockIdx.x, t = threadIdx.x;   // 128 threads
    if (b < 243) {
        int cc = b;
        float acc = 0.f;
#pragma unroll
        for (int f = 0; f < 5; f++) {
            int dig = cc % 3; cc /= 3;
            acc += __ldg(&bemb[(f * 7 + dig) * D + t]);
        }
        g_ct[b * D + t] = acc;
    } else {
        int e = (b - 243) * 128 + t;       // 0..16383
        int k = e >> 7, n = e & 127;
        g_Wt[e] = tf32r(__ldg(&W[n * D + k]));   // B[k][n] = W[n][k]
    }
}

// ---------------- aggregation (warp per node) with fused BN+ReLU of previous layer --------
__global__ void k_aggr2(int apply_bn) {
    int gid = blockIdx.x * blockDim.x + threadIdx.x;
    int node = gid >> 5, lane = gid & 31;
    if (node >= N_NODES) return;
    float4 sc = make_float4(1.f, 1.f, 1.f, 1.f);
    float4 sh = make_float4(0.f, 0.f, 0.f, 0.f);
    if (apply_bn) {
        sc = ((const float4*)g_scale)[lane];
        sh = ((const float4*)g_shift)[lane];
    }
    int s = g_off[node], e = g_off[node + 1];
    float4 acc = make_float4(0.f, 0.f, 0.f, 0.f);
    for (int j = s; j < e; j++) {
        int p = __ldg(&g_adj[j]);
        int src = p & 0xFFFF;
        int comb = p >> 16;
        float4 z = __ldg(&((const float4*)g_h)[(size_t)src * 32 + lane]);
        if (apply_bn) {
            z.x = fmaxf(z.x * sc.x + sh.x, 0.f);
            z.y = fmaxf(z.y * sc.y + sh.y, 0.f);
            z.z = fmaxf(z.z * sc.z + sh.z, 0.f);
            z.w = fmaxf(z.w * sc.w + sh.w, 0.f);
        }
        float4 c = __ldg(&((const float4*)g_ct)[(size_t)comb * 32 + lane]);
        acc.x += z.x + c.x;
        acc.y += z.y + c.y;
        acc.z += z.z + c.z;
        acc.w += z.w + c.w;
    }
    acc.x = tf32r(acc.x); acc.y = tf32r(acc.y); acc.z = tf32r(acc.z); acc.w = tf32r(acc.w);
    ((float4*)g_aggr)[(size_t)node * 32 + lane] = acc;
}

// ---------------- tf32 mma.sync GEMM: z = aggr @ W^T, fused column stats ----------------
#define SA 132                    // A smem stride (floats)
#define SB 136                    // B smem stride (floats)
#define AS_FLOATS (128 * SA)
#define BS_FLOATS (128 * SB)
#define GEMM_SMEM ((AS_FLOATS + BS_FLOATS + 256) * 4)

__global__ __launch_bounds__(256, 1) void k_gemm() {
    extern __shared__ float smem[];
    float* As = smem;
    float* Bs = smem + AS_FLOATS;
    float* ssum = smem + AS_FLOATS + BS_FLOATS;   // [128]
    float* ssq  = ssum + 128;                     // [128]
    const uint32_t* Asu = (const uint32_t*)As;
    const uint32_t* Bsu = (const uint32_t*)Bs;

    int t = threadIdx.x;
    int wid = t >> 5, lane = t & 31;
    int warpM = wid & 3, warpN = wid >> 2;        // 4 x 2 warp grid: 32 rows x 64 cols
    int row0 = blockIdx.x * 128;

    if (t < 128) { ssum[t] = 0.f; ssq[t] = 0.f; }

    const float4* A4 = (const float4*)g_aggr;
    const float4* B4 = (const float4*)g_Wt;
#pragma unroll
    for (int i = 0; i < 16; i++) {
        int idx = t + i * 256;                     // 0..4095
        int r = idx >> 5, q = idx & 31;
        int gr = row0 + r;
        float4 v = make_float4(0.f, 0.f, 0.f, 0.f);
        if (gr < N_NODES) v = __ldg(&A4[(size_t)gr * 32 + q]);
        *(float4*)&As[r * SA + q * 4] = v;
        *(float4*)&Bs[r * SB + q * 4] = __ldg(&B4[idx]);
    }
    __syncthreads();

    float c[2][8][4];
#pragma unroll
    for (int mt = 0; mt < 2; mt++)
#pragma unroll
        for (int nt = 0; nt < 8; nt++)
#pragma unroll
            for (int j = 0; j < 4; j++) c[mt][nt][j] = 0.f;

    int lr = lane >> 2, lc = lane & 3;
#pragma unroll
    for (int kk = 0; kk < 16; kk++) {
        int k0 = kk * 8;
        uint32_t a[2][4], b[8][2];
#pragma unroll
        for (int mt = 0; mt < 2; mt++) {
            int r = warpM * 32 + mt * 16 + lr;
            a[mt][0] = Asu[r * SA + k0 + lc];
            a[mt][1] = Asu[(r + 8) * SA + k0 + lc];
            a[mt][2] = Asu[r * SA + k0 + 4 + lc];
            a[mt][3] = Asu[(r + 8) * SA + k0 + 4 + lc];
        }
#pragma unroll
        for (int nt = 0; nt < 8; nt++) {
            int n = warpN * 64 + nt * 8 + lr;
            b[nt][0] = Bsu[(k0 + lc) * SB + n];
            b[nt][1] = Bsu[(k0 + 4 + lc) * SB + n];
        }
#pragma unroll
        for (int mt = 0; mt < 2; mt++)
#pragma unroll
            for (int nt = 0; nt < 8; nt++)
                mma_tf32(c[mt][nt], a[mt], b[nt]);
    }

    // ---- store z + accumulate column stats ----
#pragma unroll
    for (int mt = 0; mt < 2; mt++) {
        int r0 = row0 + warpM * 32 + mt * 16 + lr;
#pragma unroll
        for (int nt = 0; nt < 8; nt++) {
            int col = warpN * 64 + nt * 8 + lc * 2;
            if (r0 < N_NODES)
                *(float2*)&g_h[(size_t)r0 * D + col] = make_float2(c[mt][nt][0], c[mt][nt][1]);
            if (r0 + 8 < N_NODES)
                *(float2*)&g_h[(size_t)(r0 + 8) * D + col] = make_float2(c[mt][nt][2], c[mt][nt][3]);
        }
    }
#pragma unroll
    for (int nt = 0; nt < 8; nt++) {
#pragma unroll
        for (int jj = 0; jj < 2; jj++) {
            int col = warpN * 64 + nt * 8 + lc * 2 + jj;
            float v0 = c[0][nt][jj], v1 = c[0][nt][jj + 2];
            float v2 = c[1][nt][jj], v3 = c[1][nt][jj + 2];
            float s = v0 + v1 + v2 + v3;
            float q = v0 * v0 + v1 * v1 + v2 * v2 + v3 * v3;
            atomicAdd(&ssum[col], s);
            atomicAdd(&ssq[col], q);
        }
    }
    __syncthreads();
    if (t < 128) {
        g_part[(size_t)blockIdx.x * 256 + t] = ssum[t];
        g_part[(size_t)blockIdx.x * 256 + 128 + t] = ssq[t];
    }
}

// ---------------- BN finalize (reduce per-block partials) ----------------
__global__ void k_bnfin(const float* __restrict__ gamma, const float* __restrict__ beta) {
    int t = threadIdx.x;   // 128
    float s = 0.f, q = 0.f;
    for (int b = 0; b < GEMM_BLOCKS; b++) {
        s += g_part[(size_t)b * 256 + t];
        q += g_part[(size_t)b * 256 + 128 + t];
    }
    float mu = s / (float)N_NODES;
    float var = q / (float)N_NODES - mu * mu;
    float rstd = rsqrtf(fmaxf(var, 0.f) + BN_EPS);
    float sc = rstd * gamma[t];
    g_scale[t] = sc;
    g_shift[t] = beta[t] - mu * sc;
}

// ---------------- pooling (fused final BN+ReLU) ----------------
__global__ void k_bounds(const int* __restrict__ batch) {
    int t = threadIdx.x;
    if (t <= N_GRAPHS) {
        int lo = 0, hi = N_NODES;
        while (lo < hi) {
            int mid = (lo + hi) >> 1;
            if (batch[mid] < t) lo = mid + 1; else hi = mid;
        }
        g_bounds[t] = lo;
    }
}
__global__ void k_pool() {
    int g = blockIdx.x, t = threadIdx.x;
    int lo = g_bounds[g], hi = g_bounds[g + 1];
    float sc = g_scale[t], sh = g_shift[t];
    float s = 0.f;
    for (int r = lo; r < hi; r++) {
        float v = g_h[(size_t)r * D + t];
        s += fmaxf(v * sc + sh, 0.f);
    }
    int cnt = hi - lo;
    g_pool[g * D + t] = s / (float)max(cnt, 1);
}

// ---------------- MLP head ----------------
__global__ void k_mlp(const float* __restrict__ w1, const float* __restrict__ b1,
                      const float* __restrict__ w2, const float* __restrict__ b2,
                      float* __restrict__ out) {
    int g = blockIdx.x, j = threadIdx.x;   // 64 threads
    const float* gp = g_pool + g * D;
    const float* wr = w1 + j * D;
    float a = b1[j];
#pragma unroll 4
    for (int k = 0; k < D; k++) a += gp[k] * wr[k];
    a = fmaxf(a, 0.f);
    float v = a * w2[j];
#pragma unroll
    for (int o = 16; o > 0; o >>= 1) v += __shfl_down_sync(0xFFFFFFFFu, v, o);
    __shared__ float sh[2];
    if ((j & 31) == 0) sh[j >> 5] = v;
    __syncthreads();
    if (j == 0) out[g] = sh[0] + sh[1] + b2[0];
}

// ---------------- launch ----------------
extern "C" void kernel_launch(void* const* d_in, const int* in_sizes, int n_in,
                              void* d_out, int out_size) {
    const int*   x        = (const int*)d_in[0];
    const int*   ei       = (const int*)d_in[1];
    const int*   ea       = (const int*)d_in[2];
    const int*   batch    = (const int*)d_in[3];
    const float* atom_emb = (const float*)d_in[4];
    const float* bond_emb = (const float*)d_in[5];
    const float* lin_w    = (const float*)d_in[6];
    const float* bn_g     = (const float*)d_in[8];
    const float* bn_b     = (const float*)d_in[9];
    const float* w1       = (const float*)d_in[10];
    const float* b1       = (const float*)d_in[11];
    const float* w2       = (const float*)d_in[12];
    const float* b2       = (const float*)d_in[13];
    float* out = (float*)d_out;

    const int* e_src = ei;
    const int* e_dst = ei + N_EDGES;

    cudaFuncSetAttribute(k_gemm, cudaFuncAttributeMaxDynamicSharedMemorySize, GEMM_SMEM);

    k_atom<<<(N_NODES * 32 + 255) / 256, 256>>>(x, atom_emb);
    k_initdeg<<<(N_NODES + 255) / 256, 256>>>();
    k_hist<<<(N_EDGES + 255) / 256, 256>>>(e_dst);
    const int SCAN_BLOCKS = (N_NODES + 1023) / 1024;   // 49
    k_scan1<<<SCAN_BLOCKS, 1024>>>();
    k_scan2<<<1, 32>>>(SCAN_BLOCKS);
    k_scan3<<<(N_NODES + 255) / 256, 256>>>();
    k_scatter<<<(N_TOT + 255) / 256, 256>>>(e_src, e_dst, ea);

    for (int l = 0; l < NLAYER; l++) {
        k_prep<<<243 + 128, 128>>>(bond_emb + (size_t)l * 5 * 7 * D, lin_w + (size_t)l * D * D);
        k_aggr2<<<(N_NODES * 32 + 255) / 256, 256>>>(l > 0 ? 1 : 0);
        k_gemm<<<GEMM_BLOCKS, 256, GEMM_SMEM>>>();
        k_bnfin<<<1, D>>>(bn_g + l * D, bn_b + l * D);
    }

    k_bounds<<<1, 512>>>(batch);
    k_pool<<<N_GRAPHS, D>>>();
    k_mlp<<<N_GRAPHS, 64>>>(w1, b1, w2, b2, out);
}